// round 17
// baseline (speedup 1.0000x reference)
#include <cuda_runtime.h>
#include <cfloat>
#include <cstdint>

// Problem constants
#define B_   65536
#define I_   640     // input dim (K of encode GEMM)
#define L_   2560    // latent dim
#define K_   32      // top-k

// Encode tiling: block tile 64 rows x 128 cols, 128 threads, 8x8 per thread
#define BM   64
#define BN   128
#define NTHR 128
#define CH   16                 // k per pipeline chunk
#define NC   (I_ / CH)          // 40 chunks

typedef unsigned long long u64;

// ---------------------------------------------------------------------------
// Device-global scratch (no allocation allowed)
// ---------------------------------------------------------------------------
__device__ float g_WdT [(size_t)L_ * I_];  // Wd transposed  [2560][640]
__device__ u64   g_weTd[(size_t)I_ * L_];  // We^T dup-packed: [k][l]=(w,w)
__device__ float g_xT  [(size_t)I_ * B_];  // x transposed   [640][65536]

// ---------------------------------------------------------------------------
// Packed f32x2 helpers (SASS FFMA2)
// ---------------------------------------------------------------------------
__device__ __forceinline__ u64 pack2(float lo, float hi) {
    u64 d; asm("mov.b64 %0, {%1, %2};" : "=l"(d) : "f"(lo), "f"(hi)); return d;
}
__device__ __forceinline__ float2 unpack2(u64 v) {
    float2 r; asm("mov.b64 {%0, %1}, %2;" : "=f"(r.x), "=f"(r.y) : "l"(v));
    return r;
}
__device__ __forceinline__ void ffma2(u64& d, u64 a, u64 b) {
    asm("fma.rn.f32x2 %0, %1, %2, %0;" : "+l"(d) : "l"(a), "l"(b));
}
__device__ __forceinline__ uint32_t smem_u32(const void* p) {
    uint32_t a;
    asm("{ .reg .u64 t; cvta.to.shared.u64 t, %1; cvt.u32.u64 %0, t; }"
        : "=r"(a) : "l"(p));
    return a;
}
#define CP16(dst_u32, src_ptr) \
    asm volatile("cp.async.cg.shared.global [%0], [%1], 16;" \
                 :: "r"(dst_u32), "l"(src_ptr) : "memory")
#define CP_COMMIT()  asm volatile("cp.async.commit_group;" ::: "memory")
#define CP_WAIT0()   asm volatile("cp.async.wait_group 0;" ::: "memory")

// ---------------------------------------------------------------------------
// SMEM layout (byte offsets). Stage s = 20480 B: A f32 [16][64] (4 KB) +
// B dup-u64 [16][128] (16 KB).  Cs (16 KB swizzled [64][16 uint4]) overlays
// stage 0.
// ---------------------------------------------------------------------------
#define SM_STG      20480
#define SM_STAGE(s) ((s) * SM_STG)
#define SM_A_OFF    0
#define SM_B_OFF    4096
#define SM_CS       0
#define SM_SV       40960   // f32 [64][33]  8448
#define SM_SI       49408   // i16 [64][33]  4224
#define SM_BE       53632   // f32 [128]      512
#define SM_TOT      54144   // x4 CTAs = 216.6 KB <= 228 KB

// ---------------------------------------------------------------------------
// Kernel: generic 32x32 tiled transpose  dst[c][r] = src[r][c]
// ---------------------------------------------------------------------------
__global__ void transpose_kernel(const float* __restrict__ src,
                                 float* __restrict__ dst,
                                 int rows, int cols) {
    __shared__ float t[32][33];
    const int c0 = blockIdx.x * 32, r0 = blockIdx.y * 32;
    const int tx = threadIdx.x, ty = threadIdx.y;
    #pragma unroll
    for (int r = ty; r < 32; r += 8)
        t[r][tx] = src[(size_t)(r0 + r) * cols + c0 + tx];
    __syncthreads();
    #pragma unroll
    for (int r = ty; r < 32; r += 8)
        dst[(size_t)(c0 + r) * rows + r0 + tx] = t[tx][r];
}

// ---------------------------------------------------------------------------
// Kernel: transpose + dup-pack We:  g_weTd[k][l] = (We[l][k], We[l][k])
// ---------------------------------------------------------------------------
__global__ void transpose_dup_we_kernel(const float* __restrict__ We) {
    __shared__ float t[32][33];
    const int k0 = blockIdx.x * 32, l0 = blockIdx.y * 32;
    const int tx = threadIdx.x, ty = threadIdx.y;
    #pragma unroll
    for (int r = ty; r < 32; r += 8)
        t[r][tx] = We[(size_t)(l0 + r) * I_ + k0 + tx];
    __syncthreads();
    #pragma unroll
    for (int r = ty; r < 32; r += 8) {
        float v = t[tx][r];
        g_weTd[(size_t)(k0 + r) * L_ + l0 + tx] = pack2(v, v);
    }
}

// ---------------------------------------------------------------------------
// Fragment load/compute macros — ROW-PAIRED accumulators.
//   A: 2 LDS.128, reinterpreted as 4 native (row, row+1) u64 pairs (no MOVs)
//   B: 4 LDS.128 of gmem-dup-packed (b,b) u64s (no MOVs)
//   acc[i][j]: i = row pair (rows ty*8+2i, +2i+1), j = 8 n-values
// ---------------------------------------------------------------------------
#define LDA2(base, kk, Ap)                                              \
    {                                                                   \
        const ulonglong2* p =                                           \
            (const ulonglong2*)((base) + (kk) * 256 + ty * 32);         \
        ulonglong2 a0 = p[0], a1 = p[1];                                \
        (Ap)[0] = a0.x; (Ap)[1] = a0.y; (Ap)[2] = a1.x; (Ap)[3] = a1.y; \
    }
#define LDB2(base, kk, Bg)                                              \
    {                                                                   \
        const char* q = (base) + SM_B_OFF + (kk) * 1024 + tx * 32;      \
        (Bg)[0] = *(const ulonglong2*)(q);                              \
        (Bg)[1] = *(const ulonglong2*)(q + 16);                         \
        (Bg)[2] = *(const ulonglong2*)(q + 512);                        \
        (Bg)[3] = *(const ulonglong2*)(q + 528);                        \
    }
#define COMP2(Ap, Bg)                                                   \
    {                                                                   \
        _Pragma("unroll")                                               \
        for (int i = 0; i < 4; ++i) {                                   \
            ffma2(acc[i][0], (Ap)[i], (Bg)[0].x);                       \
            ffma2(acc[i][1], (Ap)[i], (Bg)[0].y);                       \
            ffma2(acc[i][2], (Ap)[i], (Bg)[1].x);                       \
            ffma2(acc[i][3], (Ap)[i], (Bg)[1].y);                       \
            ffma2(acc[i][4], (Ap)[i], (Bg)[2].x);                       \
            ffma2(acc[i][5], (Ap)[i], (Bg)[2].y);                       \
            ffma2(acc[i][6], (Ap)[i], (Bg)[3].x);                       \
            ffma2(acc[i][7], (Ap)[i], (Bg)[3].y);                       \
        }                                                               \
    }

// ---------------------------------------------------------------------------
// Kernel: exact fp32 encode GEMM (FFMA2 row-paired, cp.async 2-stage) +
//         exact streaming top-32 + scatter + FUSED sparse decode.
// ---------------------------------------------------------------------------
__global__ void __launch_bounds__(NTHR, 4)
encode_topk_kernel(const float* __restrict__ be,
                   const float* __restrict__ bd,
                   float* __restrict__ sparse_out,
                   float* __restrict__ recon) {
    extern __shared__ __align__(16) char smem[];
    const uint32_t sb = smem_u32(smem);
    uint4* CsU = (uint4*)(smem + SM_CS);   // swizzled [64][16]
    float* sv  = (float*)(smem + SM_SV);
    short* si  = (short*)(smem + SM_SI);
    float* sbe = (float*)(smem + SM_BE);

    const int tid  = threadIdx.x;
    const int tx   = tid & 15;   // col groups: tx*4 and 64+tx*4
    const int ty   = tid >> 4;   // row group: ty*8 .. ty*8+7
    const int row0 = blockIdx.x * BM;

    // init top-k lists
    for (int i = tid; i < BM * K_; i += NTHR) {
        int r = i >> 5, k = i & 31;
        sv[r * 33 + k] = -FLT_MAX;
        si[r * 33 + k] = 32767;
    }
    __syncthreads();

    // staging: chunk c -> stage s (A: 256 x 16B, B dup: 1024 x 16B)
    auto issue_chunk = [&](int ct, int c, int s) {
        const int k0   = c * CH;
        const int col0 = ct * BN;
        const uint32_t abase = sb + SM_STAGE(s) + SM_A_OFF;
        const uint32_t bbase = sb + SM_STAGE(s) + SM_B_OFF;
        #pragma unroll
        for (int it = 0; it < 2; ++it) {
            int u = tid + it * NTHR;      // 0..255
            int k = u >> 4, q = u & 15;
            const char* asrc = (const char*)(g_xT
                + (size_t)(k0 + k) * B_ + row0 + q * 4);
            CP16(abase + k * 256 + q * 16, asrc);
        }
        #pragma unroll
        for (int it = 0; it < 8; ++it) {
            int u = tid + it * NTHR;      // 0..1023
            int k = u >> 6, q = u & 63;
            const char* bsrc = (const char*)(g_weTd
                + (size_t)(k0 + k) * L_ + col0 + q * 2);
            CP16(bbase + k * 1024 + q * 16, bsrc);
        }
        CP_COMMIT();
    };

    float minv = -FLT_MAX;
    int   mini = 32767;

    issue_chunk(0, 0, 0);
    sbe[tid] = be[tid];

    for (int ct = 0; ct < L_ / BN; ++ct) {
        const int col0 = ct * BN;

        u64 acc[4][8];
        #pragma unroll
        for (int i = 0; i < 4; ++i)
            #pragma unroll
            for (int j = 0; j < 8; ++j) acc[i][j] = 0ull;

        for (int c = 0; c < NC; ++c) {
            CP_WAIT0();
            __syncthreads();            // chunk c visible; c-1 consumers done
            if (c + 1 < NC) issue_chunk(ct, c + 1, (c + 1) & 1);

            const char* base = smem + SM_STAGE(c & 1);
            #pragma unroll
            for (int k = 0; k < CH; ++k) {
                u64        Ap[4];
                ulonglong2 Bg[4];
                LDA2(base, k, Ap); LDB2(base, k, Bg);
                COMP2(Ap, Bg);
            }
            __syncthreads();            // chunk c consumed before overwrite
        }

        // two 64-col halves: epilogue (swizzled Cs over stages) + scan
        #pragma unroll
        for (int h = 0; h < 2; ++h) {
            #pragma unroll
            for (int i = 0; i < 4; ++i) {
                const int r0 = ty * 8 + 2 * i;
                float2 q0 = unpack2(acc[i][4 * h + 0]);
                float2 q1 = unpack2(acc[i][4 * h + 1]);
                float2 q2 = unpack2(acc[i][4 * h + 2]);
                float2 q3 = unpack2(acc[i][4 * h + 3]);
                const int n0 = h * 64 + tx * 4;
                float4 f0 = make_float4(q0.x + sbe[n0], q1.x + sbe[n0 + 1],
                                        q2.x + sbe[n0 + 2], q3.x + sbe[n0 + 3]);
                float4 f1 = make_float4(q0.y + sbe[n0], q1.y + sbe[n0 + 1],
                                        q2.y + sbe[n0 + 2], q3.y + sbe[n0 + 3]);
                CsU[r0 * 16 + ((tx + r0) & 15)]             = *(uint4*)&f0;
                CsU[(r0 + 1) * 16 + ((tx + r0 + 1) & 15)]   = *(uint4*)&f1;
            }
            __syncthreads();

            if (tid < BM) {
                const int lbase = tid * 33;
                #pragma unroll 1
                for (int c4 = 0; c4 < 16; ++c4) {
                    uint4 u = CsU[tid * 16 + ((c4 + tid) & 15)];
                    float4 v = *(float4*)&u;
                    float vmax = fmaxf(fmaxf(v.x, v.y), fmaxf(v.z, v.w));
                    if (vmax < minv) continue;  // exact: ties have v==minv
                    const float vs[4] = {v.x, v.y, v.z, v.w};
                    #pragma unroll 1
                    for (int e = 0; e < 4; ++e) {
                        float val = vs[e];
                        int col = col0 + h * 64 + c4 * 4 + e;
                        if (val > minv || (val == minv && col < mini)) {
                            int p = K_ - 1;
                            while (p > 0) {
                                float pv = sv[lbase + p - 1];
                                int   pi = si[lbase + p - 1];
                                if (val > pv || (val == pv && col < pi)) {
                                    sv[lbase + p] = pv;
                                    si[lbase + p] = (short)pi; --p;
                                } else break;
                            }
                            sv[lbase + p] = val; si[lbase + p] = (short)col;
                            minv = sv[lbase + K_ - 1];
                            mini = si[lbase + K_ - 1];
                        }
                    }
                }
            }
            __syncthreads();
        }

        if (ct + 1 < L_ / BN) {
            issue_chunk(ct + 1, 0, 0);
            sbe[tid] = be[col0 + BN + tid];
        }
    }

    // zero-fill this block's sparse region, then scatter winners
    {
        float4 z = make_float4(0.f, 0.f, 0.f, 0.f);
        float4* sp = (float4*)(sparse_out + (size_t)row0 * L_);
        for (int i = tid; i < BM * L_ / 4; i += NTHR) sp[i] = z;
    }
    __syncthreads();
    if (tid < BM) {
        const size_t brow = (size_t)(row0 + tid);
        #pragma unroll
        for (int k = 0; k < K_; ++k)
            sparse_out[brow * L_ + (int)si[tid * 33 + k]] = sv[tid * 33 + k];
    }

    // FUSED decode: recon[b,i] = bd[i] + sum_k v_k * WdT[idx_k, i]
    // (same fmaf chain/order as the previous standalone decode kernel)
    {
        float base5[5];
        #pragma unroll
        for (int j = 0; j < 5; ++j) base5[j] = __ldg(&bd[tid + j * 128]);
        #pragma unroll 1
        for (int r = 0; r < BM; ++r) {
            const int lb = r * 33;
            float a5[5];
            #pragma unroll
            for (int j = 0; j < 5; ++j) a5[j] = base5[j];
            #pragma unroll 4
            for (int k = 0; k < K_; ++k) {
                float v = sv[lb + k];
                const float* cw = g_WdT + (size_t)si[lb + k] * I_;
                #pragma unroll
                for (int j = 0; j < 5; ++j)
                    a5[j] = fmaf(v, __ldg(&cw[tid + j * 128]), a5[j]);
            }
            float* out = recon + (size_t)(row0 + r) * I_;
            #pragma unroll
            for (int j = 0; j < 5; ++j) out[tid + j * 128] = a5[j];
        }
    }
}

// ---------------------------------------------------------------------------
// Launch
// ---------------------------------------------------------------------------
extern "C" void kernel_launch(void* const* d_in, const int* in_sizes, int n_in,
                              void* d_out, int out_size) {
    const float* x  = (const float*)d_in[0];   // [65536, 640]
    const float* We = (const float*)d_in[1];   // [2560, 640]
    const float* be = (const float*)d_in[2];   // [2560]
    const float* Wd = (const float*)d_in[3];   // [640, 2560]
    const float* bd = (const float*)d_in[4];   // [640]

    float* recon  = (float*)d_out;                    // [B_, I_]
    float* sparse = (float*)d_out + (size_t)B_ * I_;  // [B_, L_]

    float *wdt, *xt;
    cudaGetSymbolAddress((void**)&wdt, g_WdT);
    cudaGetSymbolAddress((void**)&xt,  g_xT);

    cudaFuncSetAttribute(encode_topk_kernel,
                         cudaFuncAttributeMaxDynamicSharedMemorySize, SM_TOT);

    transpose_kernel<<<dim3(L_ / 32, I_ / 32), dim3(32, 8)>>>(Wd, wdt, I_, L_);
    transpose_dup_we_kernel<<<dim3(I_ / 32, L_ / 32), dim3(32, 8)>>>(We);
    transpose_kernel<<<dim3(I_ / 32, B_ / 32), dim3(32, 8)>>>(x, xt, B_, I_);

    encode_topk_kernel<<<B_ / BM, NTHR, SM_TOT>>>(be, bd, sparse, recon);
}